// round 1
// baseline (speedup 1.0000x reference)
#include <cuda_runtime.h>

// ---------------------------------------------------------------------------
// TensorTrain forward, right-to-left vector sweep.
//   v7[s,l]   = sum_p x[s,7,p] * core_last[l,p]
//   v_j[s,l]  = sum_{p,r} cores_mid[j][l,p,r] * x[s,j+1,p] * v_{j+1}[s,r]   (j=5..0)
//   out[s,c]  = sum_{p,r} core_first[c,p,r] * x[s,0,p] * v_0[s,r]
// All fp32; packed fma.rn.f32x2 for the dominant contraction.
// ---------------------------------------------------------------------------

namespace {

constexpr int Bn = 4096;
constexpr int Nn = 8;
constexpr int Fn = 64;
constexpr int Dn = 64;
constexpr int Cn = 10;
constexpr int NMID = 6;

constexpr int BT = 128;      // samples per CTA (mid kernel)
constexpr int KS = 8;        // split-K over p
constexpr int PC = Fn / KS;  // 8 p per chunk
constexpr int LT = 32;       // l per thread (mid kernel, 2 threads per sample)
constexpr int CSTR = 68;     // smem row stride (floats): 64 + 4 pad

// device scratch (no allocations allowed)
__device__ float g_v[Bn * Dn];                       // 1 MB chain state
__device__ float g_part[(size_t)KS * Bn * Dn];       // 8 MB split-K partials

__device__ __forceinline__ unsigned long long dup2(float a) {
  unsigned long long r;
  asm("mov.b64 %0, {%1, %1};" : "=l"(r) : "f"(a));
  return r;
}
__device__ __forceinline__ void unpack2(unsigned long long v, float& a, float& b) {
  asm("mov.b64 {%0, %1}, %2;" : "=f"(a), "=f"(b) : "l"(v));
}
__device__ __forceinline__ unsigned long long ffma2(unsigned long long a,
                                                    unsigned long long b,
                                                    unsigned long long c) {
  unsigned long long d;
  asm("fma.rn.f32x2 %0, %1, %2, %3;" : "=l"(d) : "l"(a), "l"(b), "l"(c));
  return d;
}

// ---------------------------------------------------------------------------
// v[s,l] = sum_p x[s,7,p] * core_last[l,p]
// grid: Bn/64 CTAs, 256 threads: 64 samples x 4 l-groups of 16
// ---------------------------------------------------------------------------
__global__ __launch_bounds__(256) void init_v_kernel(const float* __restrict__ x,
                                                     const float* __restrict__ clast) {
  __shared__ __align__(16) float cl[Fn * CSTR];  // [p][l], stride 68
  const int tid = threadIdx.x;
  const int sl = tid & 63;
  const int l0 = (tid >> 6) * 16;
  const int s = blockIdx.x * 64 + sl;

  // stage core_last transposed: cl[p][l] = clast[l*Fn + p]
#pragma unroll
  for (int k = 0; k < (Dn * Fn) / 256; ++k) {
    int idx = k * 256 + tid;
    int p = idx & 63;
    int l = idx >> 6;
    cl[p * CSTR + l] = clast[l * Fn + p];
  }

  float xv[Fn];
  {
    const float4* xp =
        reinterpret_cast<const float4*>(x + (size_t)s * (Nn * Fn) + 7 * Fn);
#pragma unroll
    for (int k = 0; k < Fn / 4; ++k) {
      float4 t = xp[k];
      xv[4 * k] = t.x; xv[4 * k + 1] = t.y; xv[4 * k + 2] = t.z; xv[4 * k + 3] = t.w;
    }
  }
  __syncthreads();

  unsigned long long acc[8];
#pragma unroll
  for (int q = 0; q < 8; ++q) acc[q] = 0ull;

#pragma unroll 8
  for (int p = 0; p < Fn; ++p) {
    unsigned long long t2 = dup2(xv[p]);
    const ulonglong2* rp =
        reinterpret_cast<const ulonglong2*>(&cl[p * CSTR + l0]);
#pragma unroll
    for (int q = 0; q < 4; ++q) {
      ulonglong2 cc = rp[q];
      acc[2 * q]     = ffma2(cc.x, t2, acc[2 * q]);
      acc[2 * q + 1] = ffma2(cc.y, t2, acc[2 * q + 1]);
    }
  }

  float* op = g_v + (size_t)s * Dn + l0;
#pragma unroll
  for (int q = 0; q < 8; q += 2) {
    float a, b, c, d;
    unpack2(acc[q], a, b);
    unpack2(acc[q + 1], c, d);
    reinterpret_cast<float4*>(op)[q / 2] = make_float4(a, b, c, d);
  }
}

// ---------------------------------------------------------------------------
// partial[ks][s,l] = sum_{p in chunk ks} sum_r core[l,p,r] * x[s,t,p] * v[s,r]
// grid: (Bn/BT, KS), 256 threads: 128 samples x 2 l-halves of 32
// ---------------------------------------------------------------------------
__global__ __launch_bounds__(256) void mid_step_kernel(const float* __restrict__ x,
                                                       const float* __restrict__ core,
                                                       int tIdx) {
  __shared__ __align__(16) float cs[2][Dn * CSTR];  // [r][l], stride 68, double buffered
  const int tid = threadIdx.x;
  const int sl = tid & (BT - 1);  // 0..127
  const int lh = tid >> 7;        // 0..1
  const int l0 = lh * LT;
  const int s = blockIdx.x * BT + sl;
  const int pbase = blockIdx.y * PC;

  float vr[Dn];
  {
    const float4* vp = reinterpret_cast<const float4*>(g_v + (size_t)s * Dn);
#pragma unroll
    for (int k = 0; k < Dn / 4; ++k) {
      float4 t = vp[k];
      vr[4 * k] = t.x; vr[4 * k + 1] = t.y; vr[4 * k + 2] = t.z; vr[4 * k + 3] = t.w;
    }
  }
  float xr[PC];
  {
    const float4* xp = reinterpret_cast<const float4*>(
        x + (size_t)s * (Nn * Fn) + (size_t)tIdx * Fn + pbase);
#pragma unroll
    for (int k = 0; k < PC / 4; ++k) {
      float4 t = xp[k];
      xr[4 * k] = t.x; xr[4 * k + 1] = t.y; xr[4 * k + 2] = t.z; xr[4 * k + 3] = t.w;
    }
  }

  unsigned long long acc[LT / 2];
#pragma unroll
  for (int q = 0; q < LT / 2; ++q) acc[q] = 0ull;

  // stage core[:, p, :] into cs[buf] as [r][l]
  auto stage = [&](int pp, int buf) {
    const float* cp = core + (size_t)(pbase + pp) * Dn;  // + p*64; then [l*4096 + r]
#pragma unroll
    for (int k = 0; k < (Dn * Dn) / 256; ++k) {
      int idx = k * 256 + tid;
      int r = idx & 63;
      int l = idx >> 6;
      cs[buf][r * CSTR + l] = cp[(size_t)l * (Fn * Dn) + r];
    }
  };

  stage(0, 0);
  __syncthreads();

#pragma unroll
  for (int pp = 0; pp < PC; ++pp) {
    if (pp + 1 < PC) stage(pp + 1, (pp + 1) & 1);
    const float* bufp = cs[pp & 1];
    const float xp = xr[pp];
#pragma unroll 16
    for (int r = 0; r < Dn; ++r) {
      unsigned long long t2 = dup2(xp * vr[r]);
      const ulonglong2* rp =
          reinterpret_cast<const ulonglong2*>(bufp + r * CSTR + l0);
#pragma unroll
      for (int q = 0; q < LT / 4; ++q) {
        ulonglong2 cc = rp[q];
        acc[2 * q]     = ffma2(cc.x, t2, acc[2 * q]);
        acc[2 * q + 1] = ffma2(cc.y, t2, acc[2 * q + 1]);
      }
    }
    __syncthreads();
  }

  float* op = g_part + ((size_t)blockIdx.y * Bn + s) * Dn + l0;
#pragma unroll
  for (int q = 0; q < LT / 2; q += 2) {
    float a, b, c, d;
    unpack2(acc[q], a, b);
    unpack2(acc[q + 1], c, d);
    reinterpret_cast<float4*>(op)[q / 2] = make_float4(a, b, c, d);
  }
}

// v[i] = sum_ks partial[ks][i]
__global__ void reduce_v_kernel() {
  int i = blockIdx.x * blockDim.x + threadIdx.x;
  if (i < Bn * Dn) {
    float s = 0.f;
#pragma unroll
    for (int k = 0; k < KS; ++k) s += g_part[(size_t)k * Bn * Dn + i];
    g_v[i] = s;
  }
}

// ---------------------------------------------------------------------------
// partial_out[ks][s,c] = sum_{p in chunk} sum_r cfirst[c,p,r]*x[s,0,p]*v[s,r]
// grid: (Bn/128, KS), 128 threads, 1 thread per sample
// ---------------------------------------------------------------------------
__global__ __launch_bounds__(128) void final_kernel(const float* __restrict__ x,
                                                    const float* __restrict__ cfirst) {
  __shared__ __align__(16) float fs[Dn * 12];  // [r][c], stride 12 (10 used)
  const int tid = threadIdx.x;
  const int s = blockIdx.x * 128 + tid;
  const int pbase = blockIdx.y * PC;

  float vr[Dn];
  {
    const float4* vp = reinterpret_cast<const float4*>(g_v + (size_t)s * Dn);
#pragma unroll
    for (int k = 0; k < Dn / 4; ++k) {
      float4 t = vp[k];
      vr[4 * k] = t.x; vr[4 * k + 1] = t.y; vr[4 * k + 2] = t.z; vr[4 * k + 3] = t.w;
    }
  }
  float xr[PC];
  {
    const float4* xp =
        reinterpret_cast<const float4*>(x + (size_t)s * (Nn * Fn) + pbase);
#pragma unroll
    for (int k = 0; k < PC / 4; ++k) {
      float4 t = xp[k];
      xr[4 * k] = t.x; xr[4 * k + 1] = t.y; xr[4 * k + 2] = t.z; xr[4 * k + 3] = t.w;
    }
  }

  unsigned long long acc[5];
#pragma unroll
  for (int q = 0; q < 5; ++q) acc[q] = 0ull;

#pragma unroll 1
  for (int pp = 0; pp < PC; ++pp) {
    __syncthreads();
    // stage cfirst[:, p, :] as [r][c]: 640 values, 128 threads x 5
    {
      const float* cp = cfirst + (size_t)(pbase + pp) * Dn;  // [c*4096 + r]
#pragma unroll
      for (int k = 0; k < 5; ++k) {
        int idx = k * 128 + tid;
        int r = idx & 63;
        int c = idx >> 6;  // 0..9
        fs[r * 12 + c] = cp[(size_t)c * (Fn * Dn) + r];
      }
    }
    __syncthreads();
    const float xp = xr[pp];
#pragma unroll 8
    for (int r = 0; r < Dn; ++r) {
      unsigned long long t2 = dup2(xp * vr[r]);
      const float* base = &fs[r * 12];
      ulonglong2 a01 = *reinterpret_cast<const ulonglong2*>(base);
      ulonglong2 a23 = *reinterpret_cast<const ulonglong2*>(base + 4);
      unsigned long long a4 = *reinterpret_cast<const unsigned long long*>(base + 8);
      acc[0] = ffma2(a01.x, t2, acc[0]);
      acc[1] = ffma2(a01.y, t2, acc[1]);
      acc[2] = ffma2(a23.x, t2, acc[2]);
      acc[3] = ffma2(a23.y, t2, acc[3]);
      acc[4] = ffma2(a4, t2, acc[4]);
    }
  }

  float o[10];
#pragma unroll
  for (int q = 0; q < 5; ++q) unpack2(acc[q], o[2 * q], o[2 * q + 1]);
  float* op = g_part + ((size_t)blockIdx.y * Bn + s) * 12;
  reinterpret_cast<float4*>(op)[0] = make_float4(o[0], o[1], o[2], o[3]);
  reinterpret_cast<float4*>(op)[1] = make_float4(o[4], o[5], o[6], o[7]);
  reinterpret_cast<float2*>(op + 8)[0] = make_float2(o[8], o[9]);
}

__global__ void reduce_out_kernel(float* __restrict__ out) {
  int i = blockIdx.x * blockDim.x + threadIdx.x;
  if (i < Bn * Cn) {
    int s = i / Cn;
    int c = i - s * Cn;
    float acc = 0.f;
#pragma unroll
    for (int k = 0; k < KS; ++k) acc += g_part[((size_t)k * Bn + s) * 12 + c];
    out[i] = acc;
  }
}

}  // namespace

extern "C" void kernel_launch(void* const* d_in, const int* in_sizes, int n_in,
                              void* d_out, int out_size) {
  const float* x = (const float*)d_in[0];       // (4096, 8, 64)
  const float* cfirst = (const float*)d_in[1];  // (10, 64, 64)
  const float* cmid = (const float*)d_in[2];    // (6, 64, 64, 64)
  const float* clast = (const float*)d_in[3];   // (64, 64)
  float* out = (float*)d_out;                   // (4096, 10)

  init_v_kernel<<<Bn / 64, 256>>>(x, clast);

  for (int j = NMID - 1; j >= 0; --j) {
    mid_step_kernel<<<dim3(Bn / BT, KS), 256>>>(
        x, cmid + (size_t)j * Dn * Fn * Dn, j + 1);
    reduce_v_kernel<<<(Bn * Dn) / 256, 256>>>();
  }

  final_kernel<<<dim3(Bn / 128, KS), 128>>>(x, cfirst);
  reduce_out_kernel<<<(Bn * Cn + 255) / 256, 256>>>(out);
}

// round 2
// speedup vs baseline: 1.2098x; 1.2098x over previous
#include <cuda_runtime.h>

// ---------------------------------------------------------------------------
// TensorTrain forward, right-to-left vector sweep, register-tiled GEMM style.
//   v7[r,s]   = sum_p x[s,7,p] * core_last[r,p]              (state TRANSPOSED [r][s])
//   v_j[l,s]  = sum_{p,r} cores_mid[j][l,p,r] * x[s,j+1,p] * v_{j+1}[r,s]
//   out[s,c]  = sum_{p,r} core_first[c,p,r] * x[s,0,p] * v_0[r,s]
// fp32 throughout; packed fma.rn.f32x2 / mul.rn.f32x2 for the contraction.
// ---------------------------------------------------------------------------

namespace {

constexpr int Bn = 4096;
constexpr int Nn = 8;
constexpr int Fn = 64;
constexpr int Dn = 64;
constexpr int Cn = 10;
constexpr int NMID = 6;

constexpr int KS = 16;       // split-K over p (mid kernel)
constexpr int PC = Fn / KS;  // 4 p per CTA
constexpr int KSF = 8;       // split-K over p (final kernel)
constexpr int PCF = Fn / KSF;

constexpr int VS = 132;      // smem row stride (floats) for [.][s] tiles
constexpr int SM_MID_BYTES = (2 * Dn * VS + PC * VS) * 4;  // v_t + w2 + x_t

// device scratch (no allocations allowed)
__device__ float g_v[Dn * Bn];                   // 1 MB chain state, [r][s]
__device__ float g_part[(size_t)KS * Bn * Dn];   // 16 MB split-K partials

typedef unsigned long long ull;

__device__ __forceinline__ ull dup2(float a) {
  ull r;
  asm("mov.b64 %0, {%1, %1};" : "=l"(r) : "f"(a));
  return r;
}
__device__ __forceinline__ void unpack2(ull v, float& a, float& b) {
  asm("mov.b64 {%0, %1}, %2;" : "=f"(a), "=f"(b) : "l"(v));
}
__device__ __forceinline__ ull ffma2(ull a, ull b, ull c) {
  ull d;
  asm("fma.rn.f32x2 %0, %1, %2, %3;" : "=l"(d) : "l"(a), "l"(b), "l"(c));
  return d;
}
__device__ __forceinline__ ull fmul2(ull a, ull b) {
  ull d;
  asm("mul.rn.f32x2 %0, %1, %2;" : "=l"(d) : "l"(a), "l"(b));
  return d;
}

// ---------------------------------------------------------------------------
// init: v[r,s] = sum_p x[s,7,p] * core_last[r,p]   (writes g_v transposed)
// grid: Bn/64 CTAs, 256 threads: 64 samples x 4 l-groups of 16
// ---------------------------------------------------------------------------
__global__ __launch_bounds__(256) void init_v_kernel(const float* __restrict__ x,
                                                     const float* __restrict__ clast) {
  __shared__ __align__(16) float cl[Fn * 68];  // [p][l], stride 68
  const int tid = threadIdx.x;
  const int sl = tid & 63;
  const int l0 = (tid >> 6) * 16;
  const int s = blockIdx.x * 64 + sl;

#pragma unroll
  for (int k = 0; k < (Dn * Fn) / 256; ++k) {
    int idx = k * 256 + tid;
    int p = idx & 63;
    int l = idx >> 6;
    cl[p * 68 + l] = clast[l * Fn + p];
  }

  float xv[Fn];
  {
    const float4* xp =
        reinterpret_cast<const float4*>(x + (size_t)s * (Nn * Fn) + 7 * Fn);
#pragma unroll
    for (int k = 0; k < Fn / 4; ++k) {
      float4 t = xp[k];
      xv[4 * k] = t.x; xv[4 * k + 1] = t.y; xv[4 * k + 2] = t.z; xv[4 * k + 3] = t.w;
    }
  }
  __syncthreads();

  ull acc[8];
#pragma unroll
  for (int q = 0; q < 8; ++q) acc[q] = 0ull;

#pragma unroll 8
  for (int p = 0; p < Fn; ++p) {
    ull t2 = dup2(xv[p]);
    const ulonglong2* rp = reinterpret_cast<const ulonglong2*>(&cl[p * 68 + l0]);
#pragma unroll
    for (int q = 0; q < 4; ++q) {
      ulonglong2 cc = rp[q];
      acc[2 * q]     = ffma2(cc.x, t2, acc[2 * q]);
      acc[2 * q + 1] = ffma2(cc.y, t2, acc[2 * q + 1]);
    }
  }

  // transposed store: g_v[l][s]; per-l store is coalesced across lanes (s)
#pragma unroll
  for (int q = 0; q < 8; ++q) {
    float a, b;
    unpack2(acc[q], a, b);
    g_v[(size_t)(l0 + 2 * q) * Bn + s] = a;
    g_v[(size_t)(l0 + 2 * q + 1) * Bn + s] = b;
  }
}

// ---------------------------------------------------------------------------
// mid step: partial[ks][l][s] = sum_{p in chunk} sum_r core[l,p,r]*x[s,t,p]*v[r,s]
// grid: (Bn/128, KS), 128 threads. Thread tile: 8 samples (4 pairs) x 8 l.
// smem: v_t[64][VS] ([r][s] tile), w2[64][VS] (dup'd W pairs), x_t[PC][VS].
// ---------------------------------------------------------------------------
__global__ __launch_bounds__(128) void mid_step_kernel(const float* __restrict__ x,
                                                       const float* __restrict__ core,
                                                       int tIdx) {
  extern __shared__ __align__(16) float sm[];
  float* v_t = sm;                   // [r][s] 64 x VS
  float* w2  = sm + Dn * VS;         // [r][2l] 64 x VS (128 used)
  float* x_t = sm + 2 * Dn * VS;     // [p][s] PC x VS

  const int tid = threadIdx.x;
  const int si = tid & 15;           // sample group: samples si*8 .. si*8+7
  const int li = tid >> 4;           // l group: l = li*8 .. li*8+7
  const int s0 = blockIdx.x * 128;
  const int pbase = blockIdx.y * PC;

  // stage v_t: straight row copy of g_v[r][s0..s0+127] (coalesced both ways)
#pragma unroll
  for (int it = 0; it < 16; ++it) {
    int idx = it * 128 + tid;
    int c4 = idx & 31;
    int r = idx >> 5;
    float4 t = *reinterpret_cast<const float4*>(&g_v[(size_t)r * Bn + s0 + c4 * 4]);
    *reinterpret_cast<float4*>(&v_t[r * VS + c4 * 4]) = t;
  }
  // stage x_t[p][s]
  {
    float4 t = *reinterpret_cast<const float4*>(
        x + (size_t)(s0 + tid) * (Nn * Fn) + (size_t)tIdx * Fn + pbase);
    x_t[0 * VS + tid] = t.x;
    x_t[1 * VS + tid] = t.y;
    x_t[2 * VS + tid] = t.z;
    x_t[3 * VS + tid] = t.w;
  }

  ull acc[4][8];
#pragma unroll
  for (int j = 0; j < 4; ++j)
#pragma unroll
    for (int q = 0; q < 8; ++q) acc[j][q] = 0ull;

  for (int pp = 0; pp < PC; ++pp) {
    __syncthreads();  // also covers v_t/x_t visibility on first iteration
    // stage W2: core[l][p][r] -> w2[r][2l] duplicated pairs
    {
      const float* cp = core + (size_t)(pbase + pp) * Dn;
#pragma unroll
      for (int it = 0; it < 32; ++it) {
        int idx = it * 128 + tid;
        int r = idx & 63;
        int l = idx >> 6;
        float w = cp[(size_t)l * (Fn * Dn) + r];
        *reinterpret_cast<float2*>(&w2[r * VS + 2 * l]) = make_float2(w, w);
      }
    }
    __syncthreads();

    // x pairs for this p (natural packing from x_t)
    ull xp[4];
#pragma unroll
    for (int j = 0; j < 4; ++j)
      xp[j] = *reinterpret_cast<const ull*>(&x_t[pp * VS + si * 8 + 2 * j]);

#pragma unroll 4
    for (int r = 0; r < Dn; ++r) {
      const float* vrow = &v_t[r * VS + si * 8];
      ulonglong2 va = *reinterpret_cast<const ulonglong2*>(vrow);
      ulonglong2 vb = *reinterpret_cast<const ulonglong2*>(vrow + 4);
      ull a0 = fmul2(va.x, xp[0]);
      ull a1 = fmul2(va.y, xp[1]);
      ull a2 = fmul2(vb.x, xp[2]);
      ull a3 = fmul2(vb.y, xp[3]);
      const ull* wrow = reinterpret_cast<const ull*>(&w2[r * VS + li * 16]);
#pragma unroll
      for (int q = 0; q < 8; ++q) {
        ull wq = wrow[q];
        acc[0][q] = ffma2(a0, wq, acc[0][q]);
        acc[1][q] = ffma2(a1, wq, acc[1][q]);
        acc[2][q] = ffma2(a2, wq, acc[2][q]);
        acc[3][q] = ffma2(a3, wq, acc[3][q]);
      }
    }
  }

  // store partials: g_part[ks][l][s] (pairs contiguous in s)
  float* op = g_part + (size_t)blockIdx.y * (Bn * Dn);
#pragma unroll
  for (int q = 0; q < 8; ++q) {
    int l = li * 8 + q;
#pragma unroll
    for (int j = 0; j < 4; ++j) {
      float a, b;
      unpack2(acc[j][q], a, b);
      *reinterpret_cast<float2*>(&op[(size_t)l * Bn + s0 + si * 8 + 2 * j]) =
          make_float2(a, b);
    }
  }
}

// v[i] = sum_ks partial[ks][i]  (layouts are both [l][s]-linear, index-transparent)
__global__ void reduce_v_kernel() {
  int i = blockIdx.x * blockDim.x + threadIdx.x;
  if (i < Bn * Dn) {
    float s = 0.f;
#pragma unroll
    for (int k = 0; k < KS; ++k) s += g_part[(size_t)k * Bn * Dn + i];
    g_v[i] = s;
  }
}

// ---------------------------------------------------------------------------
// final: partial_out[ks][s,c] = sum_{p in chunk} sum_r cfirst[c,p,r]*x[s,0,p]*v[r,s]
// grid: (Bn/128, KSF), 128 threads, 1 thread per sample
// ---------------------------------------------------------------------------
__global__ __launch_bounds__(128) void final_kernel(const float* __restrict__ x,
                                                    const float* __restrict__ cfirst) {
  __shared__ __align__(16) float fs[Dn * 12];  // [r][c], stride 12 (10 used)
  const int tid = threadIdx.x;
  const int s = blockIdx.x * 128 + tid;
  const int pbase = blockIdx.y * PCF;

  // v reads now from transposed g_v[r][s]: coalesced per r across lanes
  float vr[Dn];
#pragma unroll
  for (int r = 0; r < Dn; ++r) vr[r] = g_v[(size_t)r * Bn + s];

  float xr[PCF];
  {
    const float4* xp =
        reinterpret_cast<const float4*>(x + (size_t)s * (Nn * Fn) + pbase);
#pragma unroll
    for (int k = 0; k < PCF / 4; ++k) {
      float4 t = xp[k];
      xr[4 * k] = t.x; xr[4 * k + 1] = t.y; xr[4 * k + 2] = t.z; xr[4 * k + 3] = t.w;
    }
  }

  ull acc[5];
#pragma unroll
  for (int q = 0; q < 5; ++q) acc[q] = 0ull;

#pragma unroll 1
  for (int pp = 0; pp < PCF; ++pp) {
    __syncthreads();
    {
      const float* cp = cfirst + (size_t)(pbase + pp) * Dn;
#pragma unroll
      for (int k = 0; k < 5; ++k) {
        int idx = k * 128 + tid;
        int r = idx & 63;
        int c = idx >> 6;  // 0..9
        fs[r * 12 + c] = cp[(size_t)c * (Fn * Dn) + r];
      }
    }
    __syncthreads();
    const float xpv = xr[pp];
#pragma unroll 8
    for (int r = 0; r < Dn; ++r) {
      ull t2 = dup2(xpv * vr[r]);
      const float* base = &fs[r * 12];
      ulonglong2 a01 = *reinterpret_cast<const ulonglong2*>(base);
      ulonglong2 a23 = *reinterpret_cast<const ulonglong2*>(base + 4);
      ull a4 = *reinterpret_cast<const ull*>(base + 8);
      acc[0] = ffma2(a01.x, t2, acc[0]);
      acc[1] = ffma2(a01.y, t2, acc[1]);
      acc[2] = ffma2(a23.x, t2, acc[2]);
      acc[3] = ffma2(a23.y, t2, acc[3]);
      acc[4] = ffma2(a4, t2, acc[4]);
    }
  }

  float o[10];
#pragma unroll
  for (int q = 0; q < 5; ++q) unpack2(acc[q], o[2 * q], o[2 * q + 1]);
  float* op = g_part + ((size_t)blockIdx.y * Bn + s) * 12;
  reinterpret_cast<float4*>(op)[0] = make_float4(o[0], o[1], o[2], o[3]);
  reinterpret_cast<float4*>(op)[1] = make_float4(o[4], o[5], o[6], o[7]);
  reinterpret_cast<float2*>(op + 8)[0] = make_float2(o[8], o[9]);
}

__global__ void reduce_out_kernel(float* __restrict__ out) {
  int i = blockIdx.x * blockDim.x + threadIdx.x;
  if (i < Bn * Cn) {
    int s = i / Cn;
    int c = i - s * Cn;
    float acc = 0.f;
#pragma unroll
    for (int k = 0; k < KSF; ++k) acc += g_part[((size_t)k * Bn + s) * 12 + c];
    out[i] = acc;
  }
}

}  // namespace

extern "C" void kernel_launch(void* const* d_in, const int* in_sizes, int n_in,
                              void* d_out, int out_size) {
  const float* x = (const float*)d_in[0];       // (4096, 8, 64)
  const float* cfirst = (const float*)d_in[1];  // (10, 64, 64)
  const float* cmid = (const float*)d_in[2];    // (6, 64, 64, 64)
  const float* clast = (const float*)d_in[3];   // (64, 64)
  float* out = (float*)d_out;                   // (4096, 10)

  // opt-in to >48KB dynamic smem (idempotent; not an allocation)
  static bool attr_done = false;
  if (!attr_done) {
    cudaFuncSetAttribute(mid_step_kernel,
                         cudaFuncAttributeMaxDynamicSharedMemorySize,
                         SM_MID_BYTES);
    attr_done = true;
  }

  init_v_kernel<<<Bn / 64, 256>>>(x, clast);

  for (int j = NMID - 1; j >= 0; --j) {
    mid_step_kernel<<<dim3(Bn / 128, KS), 128, SM_MID_BYTES>>>(
        x, cmid + (size_t)j * Dn * Fn * Dn, j + 1);
    reduce_v_kernel<<<(Bn * Dn) / 256, 256>>>();
  }

  final_kernel<<<dim3(Bn / 128, KSF), 128>>>(x, cfirst);
  reduce_out_kernel<<<(Bn * Cn + 255) / 256, 256>>>(out);
}

// round 4
// speedup vs baseline: 1.3832x; 1.1433x over previous
#include <cuda_runtime.h>
#include <cstdint>

// ---------------------------------------------------------------------------
// TensorTrain forward, right-to-left vector sweep, fp32x2 register-tiled GEMM.
//   v7[l,s]   = sum_p x[s,7,p] * core_last[l,p]          (state stored [l][s])
//   v_j[l,s]  = sum_{p,r} cores_mid[j][l,p,r] * x[s,j+1,p] * v_{j+1}[r,s]
//   out[s,c]  = sum_{p,r} core_first[c,p,r] * x[s,0,p] * v_0[r,s]
// Mid cores pre-rearranged once to g_w2[j][p][r][2l] (value duplicated) so the
// FFMA2 b-operand streams straight from conflict-free LDS.128.
// ---------------------------------------------------------------------------

namespace {

constexpr int Bn = 4096;
constexpr int Nn = 8;
constexpr int Fn = 64;
constexpr int Dn = 64;
constexpr int Cn = 10;
constexpr int NMID = 6;

constexpr int KS = 32;       // split-K over p (mid kernel)
constexpr int PC = Fn / KS;  // 2 p per CTA
constexpr int KSF = 8;       // split-K over p (final kernel)
constexpr int PCF = Fn / KSF;

constexpr int VS = 132;      // smem row stride (floats) for v_t / x_t

// dynamic smem layout (floats): v_t[64][VS] | w2[2][64][128] | x_t[2][VS]
constexpr int SM_VT = 0;
constexpr int SM_W2 = Dn * VS;                 // 8448
constexpr int SM_XT = SM_W2 + PC * Dn * 128;   // 8448 + 16384
constexpr int SM_MID_BYTES = (SM_XT + PC * VS) * 4;

// device scratch (no allocations allowed)
__device__ float g_v[Dn * Bn];                       // 1 MB chain state, [l][s]
__device__ float g_part[(size_t)KS * Bn * Dn];       // 32 MB split-K partials
__device__ float g_w2[(size_t)NMID * Fn * Dn * 2 * Dn];  // 12.6 MB dup'd W

typedef unsigned long long ull;

__device__ __forceinline__ ull dup2(float a) {
  ull r; asm("mov.b64 %0, {%1, %1};" : "=l"(r) : "f"(a)); return r;
}
__device__ __forceinline__ void unpack2(ull v, float& a, float& b) {
  asm("mov.b64 {%0, %1}, %2;" : "=f"(a), "=f"(b) : "l"(v));
}
__device__ __forceinline__ ull ffma2(ull a, ull b, ull c) {
  ull d; asm("fma.rn.f32x2 %0, %1, %2, %3;" : "=l"(d) : "l"(a), "l"(b), "l"(c));
  return d;
}
__device__ __forceinline__ ull fmul2(ull a, ull b) {
  ull d; asm("mul.rn.f32x2 %0, %1, %2;" : "=l"(d) : "l"(a), "l"(b));
  return d;
}

// ---------------------------------------------------------------------------
// Pre-rearrange mid cores: g_w2[j][p][r][2l(+1)] = cmid[j][l][p][r], dup'd.
// One block per (j,p): 256 threads, stage [l][r] slab then write [r][2l].
// ---------------------------------------------------------------------------
__global__ __launch_bounds__(256) void preconv_w_kernel(const float* __restrict__ cmid) {
  __shared__ float tmp[Dn * 68];  // [l][r], stride 68
  const int t = threadIdx.x;
  const int p = blockIdx.x & 63;
  const int j = blockIdx.x >> 6;

  // coalesced read of cmid[j, l, p, 0..63]
#pragma unroll
  for (int it = 0; it < (Dn * Dn) / 256; ++it) {
    int idx = it * 256 + t;
    int r = idx & 63;
    int l = idx >> 6;
    tmp[l * 68 + r] = cmid[(((size_t)j * Dn + l) * Fn + p) * Dn + r];
  }
  __syncthreads();

  float* out = g_w2 + ((size_t)j * Fn + p) * (Dn * 2 * Dn);
#pragma unroll
  for (int it = 0; it < (Dn * 2 * Dn) / 256; ++it) {
    int idx = it * 256 + t;
    int col = idx & 127;   // 2l or 2l+1
    int r = idx >> 7;
    out[r * 128 + col] = tmp[(col >> 1) * 68 + r];
  }
}

// ---------------------------------------------------------------------------
// init: g_v[l][s] = sum_p x[s,7,p] * core_last[l,p]
// grid: Bn/64 CTAs, 256 threads: 64 samples x 4 l-groups of 16
// ---------------------------------------------------------------------------
__global__ __launch_bounds__(256) void init_v_kernel(const float* __restrict__ x,
                                                     const float* __restrict__ clast) {
  __shared__ __align__(16) float cl[Fn * 68];  // [p][l]
  const int tid = threadIdx.x;
  const int sl = tid & 63;
  const int l0 = (tid >> 6) * 16;
  const int s = blockIdx.x * 64 + sl;

#pragma unroll
  for (int k = 0; k < (Dn * Fn) / 256; ++k) {
    int idx = k * 256 + tid;
    int p = idx & 63;
    int l = idx >> 6;
    cl[p * 68 + l] = clast[l * Fn + p];
  }
  float xv[Fn];
  {
    const float4* xp =
        reinterpret_cast<const float4*>(x + (size_t)s * (Nn * Fn) + 7 * Fn);
#pragma unroll
    for (int k = 0; k < Fn / 4; ++k) {
      float4 t = xp[k];
      xv[4 * k] = t.x; xv[4 * k + 1] = t.y; xv[4 * k + 2] = t.z; xv[4 * k + 3] = t.w;
    }
  }
  __syncthreads();

  ull acc[8];
#pragma unroll
  for (int q = 0; q < 8; ++q) acc[q] = 0ull;
#pragma unroll 8
  for (int p = 0; p < Fn; ++p) {
    ull t2 = dup2(xv[p]);
    const ulonglong2* rp = reinterpret_cast<const ulonglong2*>(&cl[p * 68 + l0]);
#pragma unroll
    for (int q = 0; q < 4; ++q) {
      ulonglong2 cc = rp[q];
      acc[2 * q]     = ffma2(cc.x, t2, acc[2 * q]);
      acc[2 * q + 1] = ffma2(cc.y, t2, acc[2 * q + 1]);
    }
  }
#pragma unroll
  for (int q = 0; q < 8; ++q) {
    float a, b;
    unpack2(acc[q], a, b);
    g_v[(size_t)(l0 + 2 * q) * Bn + s] = a;
    g_v[(size_t)(l0 + 2 * q + 1) * Bn + s] = b;
  }
}

// ---------------------------------------------------------------------------
// mid step: partial[ks][l][s] = sum_{p in chunk} sum_r W[l,p,r]*x[s,t,p]*v[r,s]
// grid (Bn/128, KS), 128 threads. Thread tile: 8 samples (4 pairs) x 8 l.
// r-outer / p-inner; single __syncthreads; conflict-free w LDS.128.
// ---------------------------------------------------------------------------
__global__ __launch_bounds__(128) void mid_step_kernel(const float* __restrict__ x,
                                                       int j, int tIdx) {
  extern __shared__ __align__(16) float sm[];
  float* v_t = sm + SM_VT;   // [r][s], stride VS
  float* w2  = sm + SM_W2;   // [p][r][2l], stride 128
  float* x_t = sm + SM_XT;   // [p][s], stride VS

  const int tid = threadIdx.x;
  const int si = tid & 15;   // sample octet: samples si*8 .. si*8+7
  const int li = tid >> 4;   // l octet: l = li*8 .. li*8+7
  const int s0 = blockIdx.x * 128;
  const int pbase = blockIdx.y * PC;

  // stage w2 (64KB straight copy of two pre-rearranged 32KB tiles)
  {
    const float4* src = reinterpret_cast<const float4*>(
        g_w2 + ((size_t)j * Fn + pbase) * (Dn * 2 * Dn));
    float4* dst = reinterpret_cast<float4*>(w2);
#pragma unroll
    for (int it = 0; it < (PC * Dn * 2 * Dn) / (4 * 128); ++it)
      dst[it * 128 + tid] = src[it * 128 + tid];
  }
  // stage v_t: straight copy of g_v[r][s0..s0+127]
#pragma unroll
  for (int it = 0; it < 16; ++it) {
    int idx = it * 128 + tid;
    int c4 = idx & 31;
    int r = idx >> 5;
    float4 t = *reinterpret_cast<const float4*>(&g_v[(size_t)r * Bn + s0 + c4 * 4]);
    *reinterpret_cast<float4*>(&v_t[r * VS + c4 * 4]) = t;
  }
  // stage x_t[p][s]
  {
    float2 t = *reinterpret_cast<const float2*>(
        x + (size_t)(s0 + tid) * (Nn * Fn) + (size_t)tIdx * Fn + pbase);
    x_t[0 * VS + tid] = t.x;
    x_t[1 * VS + tid] = t.y;
  }
  __syncthreads();

  // x sample-pairs for both p (registers)
  ull xp0[4], xp1[4];
#pragma unroll
  for (int q = 0; q < 4; ++q) {
    xp0[q] = *reinterpret_cast<const ull*>(&x_t[0 * VS + si * 8 + 2 * q]);
    xp1[q] = *reinterpret_cast<const ull*>(&x_t[1 * VS + si * 8 + 2 * q]);
  }

  ull acc[4][8];
#pragma unroll
  for (int jj = 0; jj < 4; ++jj)
#pragma unroll
    for (int q = 0; q < 8; ++q) acc[jj][q] = 0ull;

#pragma unroll 2
  for (int r = 0; r < Dn; ++r) {
    const float* vrow = &v_t[r * VS + si * 8];
    ulonglong2 va = *reinterpret_cast<const ulonglong2*>(vrow);
    ulonglong2 vb = *reinterpret_cast<const ulonglong2*>(vrow + 4);

    // p = 0
    {
      ull a0 = fmul2(va.x, xp0[0]);
      ull a1 = fmul2(va.y, xp0[1]);
      ull a2 = fmul2(vb.x, xp0[2]);
      ull a3 = fmul2(vb.y, xp0[3]);
      const ull* wrow =
          reinterpret_cast<const ull*>(&w2[(0 * Dn + r) * 128 + li * 16]);
#pragma unroll
      for (int q = 0; q < 8; ++q) {
        ull wq = wrow[q];
        acc[0][q] = ffma2(a0, wq, acc[0][q]);
        acc[1][q] = ffma2(a1, wq, acc[1][q]);
        acc[2][q] = ffma2(a2, wq, acc[2][q]);
        acc[3][q] = ffma2(a3, wq, acc[3][q]);
      }
    }
    // p = 1
    {
      ull a0 = fmul2(va.x, xp1[0]);
      ull a1 = fmul2(va.y, xp1[1]);
      ull a2 = fmul2(vb.x, xp1[2]);
      ull a3 = fmul2(vb.y, xp1[3]);
      const ull* wrow =
          reinterpret_cast<const ull*>(&w2[(1 * Dn + r) * 128 + li * 16]);
#pragma unroll
      for (int q = 0; q < 8; ++q) {
        ull wq = wrow[q];
        acc[0][q] = ffma2(a0, wq, acc[0][q]);
        acc[1][q] = ffma2(a1, wq, acc[1][q]);
        acc[2][q] = ffma2(a2, wq, acc[2][q]);
        acc[3][q] = ffma2(a3, wq, acc[3][q]);
      }
    }
  }

  // store partials: g_part[ks][l][s]
  float* op = g_part + (size_t)blockIdx.y * (Bn * Dn);
#pragma unroll
  for (int q = 0; q < 8; ++q) {
    int l = li * 8 + q;
#pragma unroll
    for (int jj = 0; jj < 4; ++jj) {
      float a, b;
      unpack2(acc[jj][q], a, b);
      *reinterpret_cast<float2*>(&op[(size_t)l * Bn + s0 + si * 8 + 2 * jj]) =
          make_float2(a, b);
    }
  }
}

// g_v[i] = sum_ks partial[ks][i]  (both [l][s]-linear)
__global__ void reduce_v_kernel() {
  int i = blockIdx.x * blockDim.x + threadIdx.x;
  if (i < Bn * Dn) {
    float sv = 0.f;
#pragma unroll
    for (int k = 0; k < KS; ++k) sv += g_part[(size_t)k * Bn * Dn + i];
    g_v[i] = sv;
  }
}

// ---------------------------------------------------------------------------
// final: partial_out[ks][s,c] = sum_{p in chunk} sum_r cfirst[c,p,r]*x[s,0,p]*v[r,s]
// grid: (Bn/128, KSF), 128 threads, 1 thread per sample
// ---------------------------------------------------------------------------
__global__ __launch_bounds__(128) void final_kernel(const float* __restrict__ x,
                                                    const float* __restrict__ cfirst) {
  __shared__ __align__(16) float fs[Dn * 12];  // [r][c]
  const int tid = threadIdx.x;
  const int s = blockIdx.x * 128 + tid;
  const int pbase = blockIdx.y * PCF;

  float vr[Dn];
#pragma unroll
  for (int r = 0; r < Dn; ++r) vr[r] = g_v[(size_t)r * Bn + s];

  float xr[PCF];
  {
    const float4* xp =
        reinterpret_cast<const float4*>(x + (size_t)s * (Nn * Fn) + pbase);
#pragma unroll
    for (int k = 0; k < PCF / 4; ++k) {
      float4 t = xp[k];
      xr[4 * k] = t.x; xr[4 * k + 1] = t.y; xr[4 * k + 2] = t.z; xr[4 * k + 3] = t.w;
    }
  }

  ull acc[5];
#pragma unroll
  for (int q = 0; q < 5; ++q) acc[q] = 0ull;

#pragma unroll 1
  for (int pp = 0; pp < PCF; ++pp) {
    __syncthreads();
    {
      const float* cp = cfirst + (size_t)(pbase + pp) * Dn;
#pragma unroll
      for (int k = 0; k < 5; ++k) {
        int idx = k * 128 + tid;
        int r = idx & 63;
        int c = idx >> 6;
        fs[r * 12 + c] = cp[(size_t)c * (Fn * Dn) + r];
      }
    }
    __syncthreads();
    const float xpv = xr[pp];
#pragma unroll 8
    for (int r = 0; r < Dn; ++r) {
      ull t2 = dup2(xpv * vr[r]);
      const float* base = &fs[r * 12];
      ulonglong2 a01 = *reinterpret_cast<const ulonglong2*>(base);
      ulonglong2 a23 = *reinterpret_cast<const ulonglong2*>(base + 4);
      ull a4 = *reinterpret_cast<const ull*>(base + 8);
      acc[0] = ffma2(a01.x, t2, acc[0]);
      acc[1] = ffma2(a01.y, t2, acc[1]);
      acc[2] = ffma2(a23.x, t2, acc[2]);
      acc[3] = ffma2(a23.y, t2, acc[3]);
      acc[4] = ffma2(a4, t2, acc[4]);
    }
  }

  float o[10];
#pragma unroll
  for (int q = 0; q < 5; ++q) unpack2(acc[q], o[2 * q], o[2 * q + 1]);
  float* op = g_part + ((size_t)blockIdx.y * Bn + s) * 12;
  reinterpret_cast<float4*>(op)[0] = make_float4(o[0], o[1], o[2], o[3]);
  reinterpret_cast<float4*>(op)[1] = make_float4(o[4], o[5], o[6], o[7]);
  reinterpret_cast<float2*>(op + 8)[0] = make_float2(o[8], o[9]);
}

__global__ void reduce_out_kernel(float* __restrict__ out) {
  int i = blockIdx.x * blockDim.x + threadIdx.x;
  if (i < Bn * Cn) {
    int s = i / Cn;
    int c = i - s * Cn;
    float acc = 0.f;
#pragma unroll
    for (int k = 0; k < KSF; ++k) acc += g_part[((size_t)k * Bn + s) * 12 + c];
    out[i] = acc;
  }
}

}  // namespace

extern "C" void kernel_launch(void* const* d_in, const int* in_sizes, int n_in,
                              void* d_out, int out_size) {
  const float* x = (const float*)d_in[0];       // (4096, 8, 64)
  const float* cfirst = (const float*)d_in[1];  // (10, 64, 64)
  const float* cmid = (const float*)d_in[2];    // (6, 64, 64, 64)
  const float* clast = (const float*)d_in[3];   // (64, 64)
  float* out = (float*)d_out;                   // (4096, 10)

  static bool attr_done = false;
  if (!attr_done) {
    cudaFuncSetAttribute(mid_step_kernel,
                         cudaFuncAttributeMaxDynamicSharedMemorySize,
                         SM_MID_BYTES);
    attr_done = true;
  }

  preconv_w_kernel<<<NMID * Fn, 256>>>(cmid);
  init_v_kernel<<<Bn / 64, 256>>>(x, clast);

  for (int j = NMID - 1; j >= 0; --j) {
    mid_step_kernel<<<dim3(Bn / 128, KS), 128, SM_MID_BYTES>>>(x, j, j + 1);
    reduce_v_kernel<<<(Bn * Dn) / 256, 256>>>();
  }

  final_kernel<<<dim3(Bn / 128, KSF), 128>>>(x, cfirst);
  reduce_out_kernel<<<(Bn * Cn + 255) / 256, 256>>>(out);
}